// round 4
// baseline (speedup 1.0000x reference)
#include <cuda_runtime.h>
#include <cstdint>

// Motion loss on GB300: persistent blocks, cp.async double-buffered tiles,
// thread-per-(b,t) serial quaternion FK, fused deterministic reduction.
//
// Inputs: Y_m (64,2048,99) f32, X_m (64,2048,99) f32,
//         Y_t (64,24,3) f32,   X_t (64,24,3) f32
// Output: scalar f32 loss.

namespace {

constexpr int ROW     = 99;                 // floats per (b,t) row
constexpr int TR      = 64;                 // rows per tile (= threads per block)
constexpr int TPB     = 64;
constexpr int NBT     = 64 * 2048;          // 131072 rows
constexpr int NTILES  = NBT / TR;           // 2048
constexpr int GRID    = 296;                // 2 blocks/SM * 148 SMs, one wave
constexpr int TILE_F4 = TR * ROW / 4;       // 1584 float4 per array per tile
constexpr int BUF_FLT = TR * ROW;           // 6336 floats per array per tile
constexpr int SMEM_BYTES = 2 * 2 * BUF_FLT * 4;  // 2 buffers x (X,Y) = 101376 B

constexpr float S1 = 1.0f / (float(NBT) * 96.0f);  // rot mse
constexpr float S2 = 2.5f / (float(NBT) * 72.0f);  // fk  mse * 2.5
constexpr float S3 = 1.0f / (float(NBT) * 3.0f);   // pos mse

} // namespace

__device__ float    g_partials[GRID];
__device__ unsigned g_count = 0;

struct Xf { float qw, qx, qy, qz, tx, ty, tz; };

__device__ __forceinline__ void qnorm(float& w, float& x, float& y, float& z) {
    float inv = rsqrtf(w*w + x*x + y*y + z*z);
    w *= inv; x *= inv; y *= inv; z *= inv;
}

// child = parent o (local quat l, bone b); alias-safe
__device__ __forceinline__ void compose(const Xf& p,
                                        float lw, float lx, float ly, float lz,
                                        float bx, float by, float bz, Xf& o) {
    float t2x = 2.f * (p.qy * bz - p.qz * by);
    float t2y = 2.f * (p.qz * bx - p.qx * bz);
    float t2z = 2.f * (p.qx * by - p.qy * bx);
    float ntx = bx + p.qw * t2x + (p.qy * t2z - p.qz * t2y) + p.tx;
    float nty = by + p.qw * t2y + (p.qz * t2x - p.qx * t2z) + p.ty;
    float ntz = bz + p.qw * t2z + (p.qx * t2y - p.qy * t2x) + p.tz;
    float nqw = p.qw * lw - p.qx * lx - p.qy * ly - p.qz * lz;
    float nqx = p.qw * lx + lw * p.qx + (p.qy * lz - p.qz * ly);
    float nqy = p.qw * ly + lw * p.qy + (p.qz * lx - p.qx * lz);
    float nqz = p.qw * lz + lw * p.qz + (p.qx * ly - p.qy * lx);
    o.qw = nqw; o.qx = nqx; o.qy = nqy; o.qz = nqz;
    o.tx = ntx; o.ty = nty; o.tz = ntz;
}

__device__ __forceinline__ void jstep(const float* __restrict__ rx,
                                      const float* __restrict__ ry,
                                      int j,
                                      const float* __restrict__ tX,
                                      const float* __restrict__ tY,
                                      const Xf& pX, const Xf& pY,
                                      Xf& oX, Xf& oY, float& acc) {
    float xw = rx[4*j+0], xx = rx[4*j+1], xy = rx[4*j+2], xz = rx[4*j+3];
    float yw = ry[4*j+0], yx = ry[4*j+1], yy = ry[4*j+2], yz = ry[4*j+3];
    qnorm(xw, xx, xy, xz);
    qnorm(yw, yx, yy, yz);
    float d0 = xw - yw, d1 = xx - yx, d2 = xy - yy, d3 = xz - yz;
    acc += S1 * (d0*d0 + d1*d1 + d2*d2 + d3*d3);

    float bx = __ldg(tX + 3*j + 0), by = __ldg(tX + 3*j + 1), bz = __ldg(tX + 3*j + 2);
    float cx = __ldg(tY + 3*j + 0), cy = __ldg(tY + 3*j + 1), cz = __ldg(tY + 3*j + 2);
    compose(pX, xw, xx, xy, xz, bx, by, bz, oX);
    compose(pY, yw, yx, yy, yz, cx, cy, cz, oY);

    float ex = oX.tx - oY.tx, ey = oX.ty - oY.ty, ez = oX.tz - oY.tz;
    acc += S2 * (ex*ex + ey*ey + ez*ez);
}

__device__ __forceinline__ void cp16(uint32_t dst, const float4* src) {
    asm volatile("cp.async.cg.shared.global [%0], [%1], 16;\n"
                 :: "r"(dst), "l"(src));
}

// Issue loads for one tile into buffer `buf` (X then Y arrays).
__device__ __forceinline__ void issue_tile(const float* __restrict__ Xm,
                                           const float* __restrict__ Ym,
                                           int tile, int buf,
                                           uint32_t smem_base, int tid) {
    const float4* gx = (const float4*)(Xm + (size_t)tile * BUF_FLT);
    const float4* gy = (const float4*)(Ym + (size_t)tile * BUF_FLT);
    uint32_t dX = smem_base + (uint32_t)((buf * 2 + 0) * BUF_FLT * 4);
    uint32_t dY = smem_base + (uint32_t)((buf * 2 + 1) * BUF_FLT * 4);
    #pragma unroll
    for (int k = 0; k < 25; ++k) {
        int i = tid + k * TPB;
        if (i < TILE_F4) {
            cp16(dX + (uint32_t)i * 16, gx + i);
            cp16(dY + (uint32_t)i * 16, gy + i);
        }
    }
    asm volatile("cp.async.commit_group;\n" ::: "memory");
}

__device__ __forceinline__ void compute_tile(const float* __restrict__ sX,
                                             const float* __restrict__ sY,
                                             const float* __restrict__ tX,
                                             const float* __restrict__ tY,
                                             int tid, float& acc) {
    const float* rx = sX + tid * ROW;
    const float* ry = sY + tid * ROW;

    // root
    Xf X0, Y0;
    {
        float xw = rx[0], xx = rx[1], xy = rx[2], xz = rx[3];
        float yw = ry[0], yx = ry[1], yy = ry[2], yz = ry[3];
        qnorm(xw, xx, xy, xz);
        qnorm(yw, yx, yy, yz);
        float d0 = xw - yw, d1 = xx - yx, d2 = xy - yy, d3 = xz - yz;
        acc += S1 * (d0*d0 + d1*d1 + d2*d2 + d3*d3);
        X0.qw = xw; X0.qx = xx; X0.qy = xy; X0.qz = xz;
        Y0.qw = yw; Y0.qx = yx; Y0.qy = yy; Y0.qz = yz;
        X0.tx = rx[96]; X0.ty = rx[97]; X0.tz = rx[98];
        Y0.tx = ry[96]; Y0.ty = ry[97]; Y0.tz = ry[98];
        float ex = X0.tx - Y0.tx, ey = X0.ty - Y0.ty, ez = X0.tz - Y0.tz;
        acc += (S2 + S3) * (ex*ex + ey*ey + ez*ez);
    }

    Xf A, B;
    // chain 0 -> 1 -> 4 -> 7 -> 10
    jstep(rx, ry,  1, tX, tY, X0, Y0, A, B, acc);
    jstep(rx, ry,  4, tX, tY, A,  B,  A, B, acc);
    jstep(rx, ry,  7, tX, tY, A,  B,  A, B, acc);
    jstep(rx, ry, 10, tX, tY, A,  B,  A, B, acc);
    // chain 0 -> 2 -> 5 -> 8 -> 11
    jstep(rx, ry,  2, tX, tY, X0, Y0, A, B, acc);
    jstep(rx, ry,  5, tX, tY, A,  B,  A, B, acc);
    jstep(rx, ry,  8, tX, tY, A,  B,  A, B, acc);
    jstep(rx, ry, 11, tX, tY, A,  B,  A, B, acc);
    // chain 0 -> 3 -> 6 -> 9 (save G9)
    jstep(rx, ry,  3, tX, tY, X0, Y0, A, B, acc);
    jstep(rx, ry,  6, tX, tY, A,  B,  A, B, acc);
    jstep(rx, ry,  9, tX, tY, A,  B,  A, B, acc);
    Xf X9 = A, Y9 = B;
    // 9 -> 12 -> 15
    jstep(rx, ry, 12, tX, tY, X9, Y9, A, B, acc);
    jstep(rx, ry, 15, tX, tY, A,  B,  A, B, acc);
    // 9 -> 13 -> 16 -> 18 -> 20 -> 22
    jstep(rx, ry, 13, tX, tY, X9, Y9, A, B, acc);
    jstep(rx, ry, 16, tX, tY, A,  B,  A, B, acc);
    jstep(rx, ry, 18, tX, tY, A,  B,  A, B, acc);
    jstep(rx, ry, 20, tX, tY, A,  B,  A, B, acc);
    jstep(rx, ry, 22, tX, tY, A,  B,  A, B, acc);
    // 9 -> 14 -> 17 -> 19 -> 21 -> 23
    jstep(rx, ry, 14, tX, tY, X9, Y9, A, B, acc);
    jstep(rx, ry, 17, tX, tY, A,  B,  A, B, acc);
    jstep(rx, ry, 19, tX, tY, A,  B,  A, B, acc);
    jstep(rx, ry, 21, tX, tY, A,  B,  A, B, acc);
    jstep(rx, ry, 23, tX, tY, A,  B,  A, B, acc);
}

__global__ __launch_bounds__(TPB, 2)
void motion_loss_kernel(const float* __restrict__ Ym,
                        const float* __restrict__ Xm,
                        const float* __restrict__ Yt,
                        const float* __restrict__ Xt,
                        float* __restrict__ out)
{
    extern __shared__ float sm[];
    const uint32_t smem_base = (uint32_t)__cvta_generic_to_shared(sm);
    const int tid = threadIdx.x;
    const int bid = blockIdx.x;

    float acc = 0.f;

    // prologue: load first tile into buffer 0
    int t0 = bid;
    issue_tile(Xm, Ym, t0, 0, smem_base, tid);

    int buf = 0;
    for (int t = t0; t < NTILES; t += GRID) {
        const int tn = t + GRID;
        const bool has_next = (tn < NTILES);
        if (has_next) {
            issue_tile(Xm, Ym, tn, buf ^ 1, smem_base, tid);
            asm volatile("cp.async.wait_group 1;\n" ::: "memory");
        } else {
            asm volatile("cp.async.wait_group 0;\n" ::: "memory");
        }
        __syncthreads();   // all threads' copies for tile t visible

        const float* sX = sm + (buf * 2 + 0) * BUF_FLT;
        const float* sY = sm + (buf * 2 + 1) * BUF_FLT;
        const int b = t >> 5;               // 32 tiles per batch item
        compute_tile(sX, sY, Xt + b * 72, Yt + b * 72, tid, acc);

        __syncthreads();   // done reading buf before it is overwritten
        buf ^= 1;
    }

    // ---- block reduction (2 warps) ----
    const unsigned FULL = 0xffffffffu;
    #pragma unroll
    for (int o = 16; o > 0; o >>= 1) acc += __shfl_xor_sync(FULL, acc, o);

    __shared__ float wsum[2];
    __shared__ int   s_last;
    const int lane = tid & 31, wid = tid >> 5;
    if (lane == 0) wsum[wid] = acc;
    __syncthreads();

    if (tid == 0) {
        g_partials[bid] = wsum[0] + wsum[1];
        __threadfence();
        unsigned ticket = atomicAdd(&g_count, 1u);
        s_last = (ticket == GRID - 1) ? 1 : 0;
    }
    __syncthreads();

    // ---- last block: deterministic fixed-order final sum of 296 partials ----
    if (s_last) {
        double v = 0.0;
        for (int i = tid; i < GRID; i += TPB) v += (double)g_partials[i];

        __shared__ double dsum[TPB];
        dsum[tid] = v;
        __syncthreads();
        #pragma unroll
        for (int o = TPB / 2; o > 0; o >>= 1) {
            if (tid < o) dsum[tid] += dsum[tid + o];
            __syncthreads();
        }
        if (tid == 0) {
            out[0] = (float)dsum[0];
            g_count = 0;                    // reset for next graph replay
        }
    }
}

extern "C" void kernel_launch(void* const* d_in, const int* in_sizes, int n_in,
                              void* d_out, int out_size)
{
    (void)in_sizes; (void)n_in; (void)out_size;
    const float* Ym = (const float*)d_in[0];
    const float* Xm = (const float*)d_in[1];
    const float* Yt = (const float*)d_in[2];
    const float* Xt = (const float*)d_in[3];

    cudaFuncSetAttribute(motion_loss_kernel,
                         cudaFuncAttributeMaxDynamicSharedMemorySize, SMEM_BYTES);
    motion_loss_kernel<<<GRID, TPB, SMEM_BYTES>>>(Ym, Xm, Yt, Xt, (float*)d_out);
}

// round 5
// speedup vs baseline: 1.3322x; 1.3322x over previous
#include <cuda_runtime.h>
#include <cstdint>

// Motion loss on GB300: 2 threads per (b,t) row (even lane = X skeleton,
// odd lane = Y skeleton), serial quaternion FK per thread, shfl_xor pair
// exchange for loss diffs, cp.async staged tiles, fused deterministic
// reduction. 1024 blocks x 256 threads, 2 blocks/SM -> 16 warps/SM.

namespace {

constexpr int ROW   = 99;                  // floats per row
constexpr int RPB   = 128;                 // rows per block
constexpr int TPB   = 256;                 // 2 threads per row
constexpr int NBT   = 64 * 2048;           // 131072 rows
constexpr int NBLK  = NBT / RPB;           // 1024 blocks
constexpr int TILE_F4 = RPB * ROW / 4;     // 3168 float4 per array

constexpr int SY_OFF    = RPB * ROW + 16;  // +16 words: pair lanes 16 banks apart
constexpr int BONES_OFF = SY_OFF + RPB * ROW;
constexpr int SMEM_BYTES = (BONES_OFF + 160) * 4;   // ~101.8 KB

// halved loss weights (each lane of a pair accumulates the full joint loss)
constexpr float S1h = 0.5f / (float(NBT) * 96.0f);          // rot mse
constexpr float S2h = 0.5f * 2.5f / (float(NBT) * 72.0f);   // fk  mse * 2.5
constexpr float S3h = 0.5f / (float(NBT) * 3.0f);           // pos mse

} // namespace

__device__ float    g_partials[NBLK];
__device__ unsigned g_count = 0;

struct Xf { float qw, qx, qy, qz, tx, ty, tz; };

__device__ __forceinline__ void qnorm(float& w, float& x, float& y, float& z) {
    float inv = rsqrtf(w*w + x*x + y*y + z*z);
    w *= inv; x *= inv; y *= inv; z *= inv;
}

// child = parent o (local quat l, bone b)
__device__ __forceinline__ void compose(const Xf& p,
                                        float lw, float lx, float ly, float lz,
                                        float bx, float by, float bz, Xf& o) {
    float t2x = 2.f * (p.qy * bz - p.qz * by);
    float t2y = 2.f * (p.qz * bx - p.qx * bz);
    float t2z = 2.f * (p.qx * by - p.qy * bx);
    float ntx = bx + p.qw * t2x + (p.qy * t2z - p.qz * t2y) + p.tx;
    float nty = by + p.qw * t2y + (p.qz * t2x - p.qx * t2z) + p.ty;
    float ntz = bz + p.qw * t2z + (p.qx * t2y - p.qy * t2x) + p.tz;
    float nqw = p.qw * lw - p.qx * lx - p.qy * ly - p.qz * lz;
    float nqx = p.qw * lx + lw * p.qx + (p.qy * lz - p.qz * ly);
    float nqy = p.qw * ly + lw * p.qy + (p.qz * lx - p.qx * lz);
    float nqz = p.qw * lz + lw * p.qz + (p.qx * ly - p.qy * lx);
    o.qw = nqw; o.qx = nqx; o.qy = nqy; o.qz = nqz;
    o.tx = ntx; o.ty = nty; o.tz = ntz;
}

// one non-root joint for ONE skeleton; diffs cross the lane pair via shfl_xor
__device__ __forceinline__ void jstep(const float* __restrict__ r,
                                      const float* __restrict__ bn,
                                      int j,
                                      const Xf& P, Xf& O, float& acc) {
    const unsigned FULL = 0xffffffffu;
    float w = r[4*j+0], x = r[4*j+1], y = r[4*j+2], z = r[4*j+3];
    qnorm(w, x, y, z);

    float pw = __shfl_xor_sync(FULL, w, 1);
    float px = __shfl_xor_sync(FULL, x, 1);
    float py = __shfl_xor_sync(FULL, y, 1);
    float pz = __shfl_xor_sync(FULL, z, 1);
    float d0 = w - pw, d1 = x - px, d2 = y - py, d3 = z - pz;
    acc += S1h * (d0*d0 + d1*d1 + d2*d2 + d3*d3);

    float bx = bn[3*j+0], by = bn[3*j+1], bz = bn[3*j+2];
    compose(P, w, x, y, z, bx, by, bz, O);

    float ex = O.tx - __shfl_xor_sync(FULL, O.tx, 1);
    float ey = O.ty - __shfl_xor_sync(FULL, O.ty, 1);
    float ez = O.tz - __shfl_xor_sync(FULL, O.tz, 1);
    acc += S2h * (ex*ex + ey*ey + ez*ez);
}

__device__ __forceinline__ void cp16(uint32_t dst, const float4* src) {
    asm volatile("cp.async.cg.shared.global [%0], [%1], 16;\n"
                 :: "r"(dst), "l"(src));
}

__global__ __launch_bounds__(TPB, 2)
void motion_loss_kernel(const float* __restrict__ Ym,
                        const float* __restrict__ Xm,
                        const float* __restrict__ Yt,
                        const float* __restrict__ Xt,
                        float* __restrict__ out)
{
    extern __shared__ float sm[];
    const uint32_t smem_base = (uint32_t)__cvta_generic_to_shared(sm);
    const int tid = threadIdx.x;
    const int bid = blockIdx.x;

    // ---- stage 128-row tiles of Xm and Ym (flat float4, coalesced) ----
    {
        const float4* gx = (const float4*)(Xm + (size_t)bid * RPB * ROW);
        const float4* gy = (const float4*)(Ym + (size_t)bid * RPB * ROW);
        const uint32_t dX = smem_base;
        const uint32_t dY = smem_base + (uint32_t)SY_OFF * 4;
        #pragma unroll
        for (int k = 0; k < 13; ++k) {
            int i = tid + k * TPB;
            if (i < TILE_F4) {
                cp16(dX + (uint32_t)i * 16, gx + i);
                cp16(dY + (uint32_t)i * 16, gy + i);
            }
        }
        asm volatile("cp.async.commit_group;\n" ::: "memory");
    }

    // ---- stage bone tables (144 floats) for this block's batch item ----
    const int b = bid >> 4;                 // 16 blocks per batch item
    if (tid < 72)            sm[BONES_OFF + tid]      = Xt[b * 72 + tid];
    else if (tid < 144)      sm[BONES_OFF + tid]      = Yt[b * 72 + (tid - 72)];

    asm volatile("cp.async.wait_group 0;\n" ::: "memory");
    __syncthreads();

    // ---- per-thread FK over one skeleton of one row ----
    const int p    = tid >> 1;              // row within tile
    const int skel = tid & 1;               // 0 = X, 1 = Y
    const float* r  = sm + (skel ? SY_OFF : 0) + p * ROW;
    const float* bn = sm + BONES_OFF + skel * 72;

    const unsigned FULL = 0xffffffffu;
    float acc = 0.f;

    // root: quat 0 + raw position (gtr0 == pos -> pos loss folds in)
    Xf P0;
    {
        float w = r[0], x = r[1], y = r[2], z = r[3];
        qnorm(w, x, y, z);
        float pw = __shfl_xor_sync(FULL, w, 1);
        float px = __shfl_xor_sync(FULL, x, 1);
        float py = __shfl_xor_sync(FULL, y, 1);
        float pz = __shfl_xor_sync(FULL, z, 1);
        float d0 = w - pw, d1 = x - px, d2 = y - py, d3 = z - pz;
        acc += S1h * (d0*d0 + d1*d1 + d2*d2 + d3*d3);

        P0.qw = w; P0.qx = x; P0.qy = y; P0.qz = z;
        P0.tx = r[96]; P0.ty = r[97]; P0.tz = r[98];
        float ex = P0.tx - __shfl_xor_sync(FULL, P0.tx, 1);
        float ey = P0.ty - __shfl_xor_sync(FULL, P0.ty, 1);
        float ez = P0.tz - __shfl_xor_sync(FULL, P0.tz, 1);
        acc += (S2h + S3h) * (ex*ex + ey*ey + ez*ez);
    }

    Xf A;
    // chain 0 -> 1 -> 4 -> 7 -> 10
    jstep(r, bn,  1, P0, A, acc);
    jstep(r, bn,  4, A,  A, acc);
    jstep(r, bn,  7, A,  A, acc);
    jstep(r, bn, 10, A,  A, acc);
    // chain 0 -> 2 -> 5 -> 8 -> 11
    jstep(r, bn,  2, P0, A, acc);
    jstep(r, bn,  5, A,  A, acc);
    jstep(r, bn,  8, A,  A, acc);
    jstep(r, bn, 11, A,  A, acc);
    // chain 0 -> 3 -> 6 -> 9 (save G9)
    jstep(r, bn,  3, P0, A, acc);
    jstep(r, bn,  6, A,  A, acc);
    jstep(r, bn,  9, A,  A, acc);
    Xf P9 = A;
    // 9 -> 12 -> 15
    jstep(r, bn, 12, P9, A, acc);
    jstep(r, bn, 15, A,  A, acc);
    // 9 -> 13 -> 16 -> 18 -> 20 -> 22
    jstep(r, bn, 13, P9, A, acc);
    jstep(r, bn, 16, A,  A, acc);
    jstep(r, bn, 18, A,  A, acc);
    jstep(r, bn, 20, A,  A, acc);
    jstep(r, bn, 22, A,  A, acc);
    // 9 -> 14 -> 17 -> 19 -> 21 -> 23
    jstep(r, bn, 14, P9, A, acc);
    jstep(r, bn, 17, A,  A, acc);
    jstep(r, bn, 19, A,  A, acc);
    jstep(r, bn, 21, A,  A, acc);
    jstep(r, bn, 23, A,  A, acc);

    // ---- block reduction (8 warps) ----
    #pragma unroll
    for (int o = 16; o > 0; o >>= 1) acc += __shfl_xor_sync(FULL, acc, o);

    __shared__ float wsum[8];
    __shared__ int   s_last;
    const int lane = tid & 31, wid = tid >> 5;
    if (lane == 0) wsum[wid] = acc;
    __syncthreads();

    if (tid == 0) {
        float s = 0.f;
        #pragma unroll
        for (int i = 0; i < 8; ++i) s += wsum[i];
        g_partials[bid] = s;
        __threadfence();
        unsigned ticket = atomicAdd(&g_count, 1u);
        s_last = (ticket == NBLK - 1) ? 1 : 0;
    }
    __syncthreads();

    // ---- last block: deterministic fixed-order final sum ----
    if (s_last) {
        double v = 0.0;
        #pragma unroll
        for (int k = 0; k < NBLK / TPB; ++k)     // 4 per thread
            v += (double)g_partials[tid + k * TPB];

        __shared__ double dsum[TPB];
        dsum[tid] = v;
        __syncthreads();
        #pragma unroll
        for (int o = TPB / 2; o > 0; o >>= 1) {
            if (tid < o) dsum[tid] += dsum[tid + o];
            __syncthreads();
        }
        if (tid == 0) {
            out[0] = (float)dsum[0];
            g_count = 0;                          // reset for next graph replay
        }
    }
}

extern "C" void kernel_launch(void* const* d_in, const int* in_sizes, int n_in,
                              void* d_out, int out_size)
{
    (void)in_sizes; (void)n_in; (void)out_size;
    const float* Ym = (const float*)d_in[0];
    const float* Xm = (const float*)d_in[1];
    const float* Yt = (const float*)d_in[2];
    const float* Xt = (const float*)d_in[3];

    cudaFuncSetAttribute(motion_loss_kernel,
                         cudaFuncAttributeMaxDynamicSharedMemorySize, SMEM_BYTES);
    motion_loss_kernel<<<NBLK, TPB, SMEM_BYTES>>>(Ym, Xm, Yt, Xt, (float*)d_out);
}